// round 2
// baseline (speedup 1.0000x reference)
#include <cuda_runtime.h>
#include <cstdint>

// Problem constants
#define B_ 4
#define L_ 4096
#define DIM_ 1024
#define H_ 16
#define NCHUNK_ 64
#define CHUNK_ 64
#define M_ (B_ * L_)          // 16384

// ---------------------------------------------------------------------------
// Device scratch (allocation-free contract: __device__ globals)
// ---------------------------------------------------------------------------
__device__ float g_q[(size_t)B_ * L_ * 1024];
__device__ float g_k[(size_t)B_ * L_ * 1024];
__device__ float g_v[(size_t)B_ * L_ * 1024];
__device__ float g_o[(size_t)B_ * L_ * 1024];
__device__ float g_lrwd[B_ * NCHUNK_ * 64];   // per (b,chunk): [0:16)=lr_in,[16:32)=lr_out,[32:48)=wd_in,[48:64)=wd_out

// ---------------------------------------------------------------------------
// SGEMM (NT): C[M,N] = A[M,K] @ W[N,K]^T, optional SiLU epilogue.
// 128x128 block tile, BK=8, 256 threads, 8x8 per thread, warp tile 64x32.
// ---------------------------------------------------------------------------
__global__ __launch_bounds__(256, 2)
void sgemm_nt(const float* __restrict__ A, const float* __restrict__ W,
              float* __restrict__ C, int M, int N, int K, int act)
{
    __shared__ float As[8][128];
    __shared__ float Bs[8][128];

    const int t  = threadIdx.x;
    const int bm = blockIdx.y * 128;
    const int bn = blockIdx.x * 128;

    // global -> smem load mapping: each thread loads one float4 of A and W
    const int lr = t >> 1;            // 0..127
    const int lc = (t & 1) * 4;       // 0 or 4
    const float* Ag = A + (size_t)(bm + lr) * K + lc;
    const float* Wg = W + (size_t)(bn + lr) * K + lc;

    // compute mapping: 8 warps in 2(m) x 4(n); warp tile 64x32; thread tile 8x8
    const int w    = t >> 5;
    const int lane = t & 31;
    const int tm0  = (w >> 2) * 64 + (lane & 7) * 8;
    const int tn0  = (w & 3) * 32 + (lane >> 3) * 8;

    float acc[8][8];
#pragma unroll
    for (int i = 0; i < 8; i++)
#pragma unroll
        for (int j = 0; j < 8; j++) acc[i][j] = 0.f;

    for (int k0 = 0; k0 < K; k0 += 8) {
        float4 av = *(const float4*)(Ag + k0);
        float4 wv = *(const float4*)(Wg + k0);
        As[lc + 0][lr] = av.x; As[lc + 1][lr] = av.y;
        As[lc + 2][lr] = av.z; As[lc + 3][lr] = av.w;
        Bs[lc + 0][lr] = wv.x; Bs[lc + 1][lr] = wv.y;
        Bs[lc + 2][lr] = wv.z; Bs[lc + 3][lr] = wv.w;
        __syncthreads();

#pragma unroll
        for (int k = 0; k < 8; k++) {
            float4 a0 = *(const float4*)&As[k][tm0];
            float4 a1 = *(const float4*)&As[k][tm0 + 4];
            float4 b0 = *(const float4*)&Bs[k][tn0];
            float4 b1 = *(const float4*)&Bs[k][tn0 + 4];
            float a[8] = {a0.x, a0.y, a0.z, a0.w, a1.x, a1.y, a1.z, a1.w};
            float b[8] = {b0.x, b0.y, b0.z, b0.w, b1.x, b1.y, b1.z, b1.w};
#pragma unroll
            for (int i = 0; i < 8; i++)
#pragma unroll
                for (int j = 0; j < 8; j++) acc[i][j] += a[i] * b[j];
        }
        __syncthreads();
    }

#pragma unroll
    for (int i = 0; i < 8; i++) {
        float* Crow = C + (size_t)(bm + tm0 + i) * N + bn + tn0;
#pragma unroll
        for (int j = 0; j < 8; j++) {
            float v = acc[i][j];
            if (act == 1) v = v / (1.f + __expf(-v));   // SiLU
            Crow[j] = v;
        }
    }
}

// ---------------------------------------------------------------------------
// lr/wd chunk means:
// For each (b, chunk): lrwd[j] = mean_n sigmoid(x[token n] . Wcat[j]) * scale_j
//   j in [0,32) -> Wlr rows (scale 1e-3), j in [32,64) -> Wbeta rows (scale 0.9)
// Deterministic reduction (no atomics).
// ---------------------------------------------------------------------------
__global__ __launch_bounds__(256, 2)
void lrwd_kernel(const float* __restrict__ x,
                 const float* __restrict__ Wlr,
                 const float* __restrict__ Wbeta)
{
    __shared__ float xs[64][65];
    __shared__ float ws[64][65];
    __shared__ float red2[64 * 16];   // [j][r0]

    const int bc = blockIdx.x;                    // b*64 + chunk
    const size_t xb = (size_t)bc * 64 * 1024;     // chunk token 0
    const int t  = threadIdx.x;
    const int r0 = t >> 4;    // 0..15
    const int c0 = t & 15;    // 0..15

    float acc[4][4];
#pragma unroll
    for (int i = 0; i < 4; i++)
#pragma unroll
        for (int j = 0; j < 4; j++) acc[i][j] = 0.f;

    for (int k0 = 0; k0 < 1024; k0 += 64) {
        for (int i = t; i < 4096; i += 256) {
            int n = i >> 6, d = i & 63;
            xs[n][d] = x[xb + (size_t)n * 1024 + k0 + d];
            ws[n][d] = (n < 32) ? Wlr[n * 1024 + k0 + d]
                                : Wbeta[(n - 32) * 1024 + k0 + d];
        }
        __syncthreads();
#pragma unroll 4
        for (int k = 0; k < 64; k++) {
            float a[4], b[4];
#pragma unroll
            for (int ii = 0; ii < 4; ii++) a[ii] = xs[r0 + 16 * ii][k];
#pragma unroll
            for (int jj = 0; jj < 4; jj++) b[jj] = ws[c0 + 16 * jj][k];
#pragma unroll
            for (int ii = 0; ii < 4; ii++)
#pragma unroll
                for (int jj = 0; jj < 4; jj++) acc[ii][jj] += a[ii] * b[jj];
        }
        __syncthreads();
    }

    // sigmoid + scale, deterministic tree-reduce over tokens
#pragma unroll
    for (int jj = 0; jj < 4; jj++) {
        int j = c0 + 16 * jj;
        float scale = (j < 32) ? 0.001f : 0.9f;
        float p = 0.f;
#pragma unroll
        for (int ii = 0; ii < 4; ii++)
            p += scale / (1.f + __expf(-acc[ii][jj]));
        red2[j * 16 + r0] = p;
    }
    __syncthreads();
    if (t < 64) {
        float s = 0.f;
        for (int r = 0; r < 16; r++) s += red2[t * 16 + r];
        g_lrwd[bc * 64 + t] = s * (1.f / 64.f);
    }
}

// ---------------------------------------------------------------------------
// Persistent scan: 64 CTAs, one per (b,h). W_in/W_out live in smem across
// all 64 chunks. All 64x64 GEMM-lets: 4x4 register tile, stride-16 lane
// interleave (conflict-free on the lane-varying operand; pad 65 => bank =
// (row+col)%32).
// ---------------------------------------------------------------------------
#define PAD 65

__global__ __launch_bounds__(256, 1)
void scan_kernel(const float* __restrict__ Win0, const float* __restrict__ Wout0)
{
    extern __shared__ float sm[];
    float* Wi  = sm;                 // [64][65] W_in
    float* Wo_ = sm + 64 * PAD;      // W_out
    float* QK  = sm + 2 * 64 * PAD;  // q tile, then k tile
    float* Vv  = sm + 3 * 64 * PAD;  // v tile
    float* Pm  = sm + 4 * 64 * PAD;  // probs
    float* Am  = sm + 5 * 64 * PAD;  // a, then g_z
    float* red = sm + 6 * 64 * PAD;  // [4][64]
    float* cs  = red + 256;          // [64] softmax col stats
    float* sv  = cs + 64;            // [64] s values

    const int b = blockIdx.x >> 4;
    const int h = blockIdx.x & 15;
    const int t = threadIdx.x;
    const int r0 = t >> 4;   // 0..15
    const int c0 = t & 15;   // 0..15

    // init state from W_in_init/W_out_init: shape (1, DINNER, H, DQK)
    for (int i = t; i < 4096; i += 256) {
        int D = i >> 6, d = i & 63;
        Wi [D * PAD + d] = Win0 [D * 1024 + h * 64 + d];
        Wo_[D * PAD + d] = Wout0[D * 1024 + h * 64 + d];
    }
    __syncthreads();

    for (int c = 0; c < NCHUNK_; c++) {
        const size_t base = ((size_t)b * L_ + (size_t)c * 64) * 1024 + h * 64;
        const int lb = (b * 64 + c) * 64;
        const float li  = g_lrwd[lb + h];
        const float lo  = g_lrwd[lb + 16 + h];
        const float wdi = g_lrwd[lb + 32 + h];
        const float wdo = g_lrwd[lb + 48 + h];

        // load q, v tiles
        for (int i = t; i < 4096; i += 256) {
            int n = i >> 6, d = i & 63;
            QK[n * PAD + d] = g_q[base + (size_t)n * 1024 + d];
            Vv[n * PAD + d] = g_v[base + (size_t)n * 1024 + d];
        }
        __syncthreads();

        // logits_q: Pm[n][D] = sum_d q[n][d] * Wi[D][d]   (NT)
        {
            float acc[4][4];
#pragma unroll
            for (int ii = 0; ii < 4; ii++)
#pragma unroll
                for (int jj = 0; jj < 4; jj++) acc[ii][jj] = 0.f;
#pragma unroll 4
            for (int k = 0; k < 64; k++) {
                float a[4], bb[4];
#pragma unroll
                for (int ii = 0; ii < 4; ii++) a[ii]  = QK[(r0 + 16 * ii) * PAD + k];
#pragma unroll
                for (int jj = 0; jj < 4; jj++) bb[jj] = Wi[(c0 + 16 * jj) * PAD + k];
#pragma unroll
                for (int ii = 0; ii < 4; ii++)
#pragma unroll
                    for (int jj = 0; jj < 4; jj++) acc[ii][jj] += a[ii] * bb[jj];
            }
#pragma unroll
            for (int ii = 0; ii < 4; ii++)
#pragma unroll
                for (int jj = 0; jj < 4; jj++)
                    Pm[(r0 + 16 * ii) * PAD + c0 + 16 * jj] = acc[ii][jj];
        }
        __syncthreads();

        // softmax over n (rows) per column D  -- pass 1 (for p_q)
        {
            int q = t >> 6, D = t & 63;
            float m = -1e30f;
            for (int n = q * 16; n < q * 16 + 16; n++) m = fmaxf(m, Pm[n * PAD + D]);
            red[q * 64 + D] = m;
        }
        __syncthreads();
        if (t < 64)
            cs[t] = fmaxf(fmaxf(red[t], red[64 + t]), fmaxf(red[128 + t], red[192 + t]));
        __syncthreads();
        {
            int q = t >> 6, D = t & 63;
            float m = cs[D], s = 0.f;
            for (int n = q * 16; n < q * 16 + 16; n++) {
                float e = __expf(Pm[n * PAD + D] - m);
                Pm[n * PAD + D] = e;
                s += e;
            }
            red[q * 64 + D] = s;
        }
        __syncthreads();
        if (t < 64) cs[t] = 1.f / (red[t] + red[64 + t] + red[128 + t] + red[192 + t]);
        __syncthreads();
        {
            int q = t >> 6, D = t & 63;
            float inv = cs[D];
            for (int n = q * 16; n < q * 16 + 16; n++) Pm[n * PAD + D] *= inv;
        }
        __syncthreads();

        // o[n][d] = sum_D Pm[n][D] * Wo_[D][d]  (NN) -> global
        {
            float acc[4][4];
#pragma unroll
            for (int ii = 0; ii < 4; ii++)
#pragma unroll
                for (int jj = 0; jj < 4; jj++) acc[ii][jj] = 0.f;
#pragma unroll 4
            for (int k = 0; k < 64; k++) {
                float a[4], bb[4];
#pragma unroll
                for (int ii = 0; ii < 4; ii++) a[ii]  = Pm[(r0 + 16 * ii) * PAD + k];
#pragma unroll
                for (int jj = 0; jj < 4; jj++) bb[jj] = Wo_[k * PAD + c0 + 16 * jj];
#pragma unroll
                for (int ii = 0; ii < 4; ii++)
#pragma unroll
                    for (int jj = 0; jj < 4; jj++) acc[ii][jj] += a[ii] * bb[jj];
            }
#pragma unroll
            for (int ii = 0; ii < 4; ii++)
#pragma unroll
                for (int jj = 0; jj < 4; jj++)
                    g_o[base + (size_t)(r0 + 16 * ii) * 1024 + c0 + 16 * jj] = acc[ii][jj];
        }

        // load k tile (overwrites QK; Pm reads above completed at next barrier)
        for (int i = t; i < 4096; i += 256) {
            int n = i >> 6, d = i & 63;
            QK[n * PAD + d] = g_k[base + (size_t)n * 1024 + d];
        }
        __syncthreads();

        // logits_k: Pm[n][D] = sum_d k[n][d] * Wi[D][d]  (NT)
        {
            float acc[4][4];
#pragma unroll
            for (int ii = 0; ii < 4; ii++)
#pragma unroll
                for (int jj = 0; jj < 4; jj++) acc[ii][jj] = 0.f;
#pragma unroll 4
            for (int k = 0; k < 64; k++) {
                float a[4], bb[4];
#pragma unroll
                for (int ii = 0; ii < 4; ii++) a[ii]  = QK[(r0 + 16 * ii) * PAD + k];
#pragma unroll
                for (int jj = 0; jj < 4; jj++) bb[jj] = Wi[(c0 + 16 * jj) * PAD + k];
#pragma unroll
                for (int ii = 0; ii < 4; ii++)
#pragma unroll
                    for (int jj = 0; jj < 4; jj++) acc[ii][jj] += a[ii] * bb[jj];
            }
#pragma unroll
            for (int ii = 0; ii < 4; ii++)
#pragma unroll
                for (int jj = 0; jj < 4; jj++)
                    Pm[(r0 + 16 * ii) * PAD + c0 + 16 * jj] = acc[ii][jj];
        }
        __syncthreads();

        // softmax pass 2 (for p)
        {
            int q = t >> 6, D = t & 63;
            float m = -1e30f;
            for (int n = q * 16; n < q * 16 + 16; n++) m = fmaxf(m, Pm[n * PAD + D]);
            red[q * 64 + D] = m;
        }
        __syncthreads();
        if (t < 64)
            cs[t] = fmaxf(fmaxf(red[t], red[64 + t]), fmaxf(red[128 + t], red[192 + t]));
        __syncthreads();
        {
            int q = t >> 6, D = t & 63;
            float m = cs[D], s = 0.f;
            for (int n = q * 16; n < q * 16 + 16; n++) {
                float e = __expf(Pm[n * PAD + D] - m);
                Pm[n * PAD + D] = e;
                s += e;
            }
            red[q * 64 + D] = s;
        }
        __syncthreads();
        if (t < 64) cs[t] = 1.f / (red[t] + red[64 + t] + red[128 + t] + red[192 + t]);
        __syncthreads();
        {
            int q = t >> 6, D = t & 63;
            float inv = cs[D];
            for (int n = q * 16; n < q * 16 + 16; n++) Pm[n * PAD + D] *= inv;
        }
        __syncthreads();

        // a[n][D] = sum_d v[n][d] * Wo_[D][d]  (NT) -> Am
        {
            float acc[4][4];
#pragma unroll
            for (int ii = 0; ii < 4; ii++)
#pragma unroll
                for (int jj = 0; jj < 4; jj++) acc[ii][jj] = 0.f;
#pragma unroll 4
            for (int k = 0; k < 64; k++) {
                float a[4], bb[4];
#pragma unroll
                for (int ii = 0; ii < 4; ii++) a[ii]  = Vv[(r0 + 16 * ii) * PAD + k];
#pragma unroll
                for (int jj = 0; jj < 4; jj++) bb[jj] = Wo_[(c0 + 16 * jj) * PAD + k];
#pragma unroll
                for (int ii = 0; ii < 4; ii++)
#pragma unroll
                    for (int jj = 0; jj < 4; jj++) acc[ii][jj] += a[ii] * bb[jj];
            }
#pragma unroll
            for (int ii = 0; ii < 4; ii++)
#pragma unroll
                for (int jj = 0; jj < 4; jj++)
                    Am[(r0 + 16 * ii) * PAD + c0 + 16 * jj] = acc[ii][jj];
        }
        __syncthreads();

        // s[n] = sum_D p*a ; then g_z into Am
        if (t < 64) {
            float s = 0.f;
            for (int D = 0; D < 64; D++) s += Pm[t * PAD + D] * Am[t * PAD + D];
            sv[t] = s;
        }
        __syncthreads();
        for (int i = t; i < 4096; i += 256) {
            int n = i >> 6, D = i & 63;
            Am[n * PAD + D] = -Pm[n * PAD + D] * (Am[n * PAD + D] - sv[n]);
        }
        __syncthreads();

        // fused updates (TN):
        //   W_in[D][d]  = wdi*W_in  - li * sum_n k[n][d] * g_z[n][D]
        //   W_out[D][d] = wdo*W_out + lo * sum_n p[n][D] * v[n][d]
        {
            float gin[4][4], gout[4][4];
#pragma unroll
            for (int ii = 0; ii < 4; ii++)
#pragma unroll
                for (int jj = 0; jj < 4; jj++) { gin[ii][jj] = 0.f; gout[ii][jj] = 0.f; }
#pragma unroll 4
            for (int n = 0; n < 64; n++) {
                float gz[4], pp[4], kk[4], vv[4];
#pragma unroll
                for (int ii = 0; ii < 4; ii++) {
                    gz[ii] = Am[n * PAD + r0 + 16 * ii];
                    pp[ii] = Pm[n * PAD + r0 + 16 * ii];
                }
#pragma unroll
                for (int jj = 0; jj < 4; jj++) {
                    kk[jj] = QK[n * PAD + c0 + 16 * jj];
                    vv[jj] = Vv[n * PAD + c0 + 16 * jj];
                }
#pragma unroll
                for (int ii = 0; ii < 4; ii++)
#pragma unroll
                    for (int jj = 0; jj < 4; jj++) {
                        gin[ii][jj]  += gz[ii] * kk[jj];
                        gout[ii][jj] += pp[ii] * vv[jj];
                    }
            }
#pragma unroll
            for (int ii = 0; ii < 4; ii++)
#pragma unroll
                for (int jj = 0; jj < 4; jj++) {
                    int idx = (r0 + 16 * ii) * PAD + c0 + 16 * jj;
                    Wi [idx] = wdi * Wi [idx] - li * gin[ii][jj];
                    Wo_[idx] = wdo * Wo_[idx] + lo * gout[ii][jj];
                }
        }
        __syncthreads();
    }
}

// ---------------------------------------------------------------------------
// Launch
// ---------------------------------------------------------------------------
extern "C" void kernel_launch(void* const* d_in, const int* in_sizes, int n_in,
                              void* d_out, int out_size)
{
    (void)in_sizes; (void)n_in; (void)out_size;
    const float* x     = (const float*)d_in[0];
    const float* Wq    = (const float*)d_in[1];
    const float* Wk    = (const float*)d_in[2];
    const float* Wv    = (const float*)d_in[3];
    const float* Wlr   = (const float*)d_in[4];
    const float* Wbeta = (const float*)d_in[5];
    const float* Wo    = (const float*)d_in[6];
    const float* Win0  = (const float*)d_in[7];
    const float* Wout0 = (const float*)d_in[8];
    float* out = (float*)d_out;

    float *q, *k, *v, *om;
    cudaGetSymbolAddress((void**)&q,  g_q);
    cudaGetSymbolAddress((void**)&k,  g_k);
    cudaGetSymbolAddress((void**)&v,  g_v);
    cudaGetSymbolAddress((void**)&om, g_o);

    dim3 grid(1024 / 128, M_ / 128);
    sgemm_nt<<<grid, 256>>>(x, Wq, q, M_, 1024, 1024, 1);
    sgemm_nt<<<grid, 256>>>(x, Wk, k, M_, 1024, 1024, 1);
    sgemm_nt<<<grid, 256>>>(x, Wv, v, M_, 1024, 1024, 0);
    lrwd_kernel<<<B_ * NCHUNK_, 256>>>(x, Wlr, Wbeta);

    const int smem_bytes = (6 * 64 * PAD + 256 + 64 + 64) * (int)sizeof(float);
    cudaFuncSetAttribute(scan_kernel, cudaFuncAttributeMaxDynamicSharedMemorySize, smem_bytes);
    scan_kernel<<<64, 256, smem_bytes>>>(Win0, Wout0);

    sgemm_nt<<<grid, 256>>>(om, Wo, out, M_, 1024, 1024, 0);
}

// round 3
// speedup vs baseline: 1.8260x; 1.8260x over previous
#include <cuda_runtime.h>
#include <cstdint>

// Problem constants
#define B_ 4
#define L_ 4096
#define DIM_ 1024
#define H_ 16
#define NCHUNK_ 64
#define CHUNK_ 64
#define M_ (B_ * L_)          // 16384

// ---------------------------------------------------------------------------
// Device scratch (allocation-free contract: __device__ globals)
// ---------------------------------------------------------------------------
__device__ float g_q[(size_t)B_ * L_ * 1024];
__device__ float g_k[(size_t)B_ * L_ * 1024];
__device__ float g_v[(size_t)B_ * L_ * 1024];
__device__ float g_o[(size_t)B_ * L_ * 1024];
__device__ float g_lrwd[B_ * NCHUNK_ * 64];

// ---------------------------------------------------------------------------
// Small PTX helpers
// ---------------------------------------------------------------------------
__device__ __forceinline__ uint32_t cvt_tf32(float f) {
    uint32_t u;
    asm("cvt.rna.tf32.f32 %0, %1;" : "=r"(u) : "f"(f));
    return u;
}

__device__ __forceinline__ void cp16(void* smem, const void* gmem) {
    uint32_t s = (uint32_t)__cvta_generic_to_shared(smem);
    asm volatile("cp.async.cg.shared.global [%0], [%1], 16;" :: "r"(s), "l"(gmem));
}
__device__ __forceinline__ void cp_commit() {
    asm volatile("cp.async.commit_group;");
}
template <int N>
__device__ __forceinline__ void cp_wait() {
    asm volatile("cp.async.wait_group %0;" :: "n"(N));
}

__device__ __forceinline__ void mma_tf32(float c[4],
                                         uint32_t a0, uint32_t a1, uint32_t a2, uint32_t a3,
                                         uint32_t b0, uint32_t b1) {
    asm volatile(
        "mma.sync.aligned.m16n8k8.row.col.f32.tf32.tf32.f32 "
        "{%0,%1,%2,%3}, {%4,%5,%6,%7}, {%8,%9}, {%0,%1,%2,%3};"
        : "+f"(c[0]), "+f"(c[1]), "+f"(c[2]), "+f"(c[3])
        : "r"(a0), "r"(a1), "r"(a2), "r"(a3), "r"(b0), "r"(b1));
}

// ---------------------------------------------------------------------------
// TF32 tensor-core GEMM (NT): C[M,N] = A[M,K] @ W[N,K]^T, optional SiLU.
// 128x128 block, BK=16, 256 threads, warp tile 64x32 (4x4 m16n8k8),
// cp.async double-buffered. Smem row pitch 20 floats => conflict-free
// fragment loads (banks (20*g + t4) mod 32 all distinct).
// ---------------------------------------------------------------------------
template <int ACT>
__global__ __launch_bounds__(256)
void gemm_tf32(const float* __restrict__ A, const float* __restrict__ W,
               float* __restrict__ C, int M, int N, int K)
{
    __shared__ __align__(16) float As[2][128][20];
    __shared__ __align__(16) float Bs[2][128][20];

    const int t    = threadIdx.x;
    const int bm   = blockIdx.y * 128;
    const int bn   = blockIdx.x * 128;
    const int w    = t >> 5;
    const int lane = t & 31;
    const int wm   = (w >> 2) * 64;
    const int wn   = (w & 3) * 32;
    const int g    = lane >> 2;
    const int t4   = lane & 3;

    float acc[4][4][4];
#pragma unroll
    for (int mt = 0; mt < 4; mt++)
#pragma unroll
        for (int nt = 0; nt < 4; nt++)
#pragma unroll
            for (int c = 0; c < 4; c++) acc[mt][nt][c] = 0.f;

    const int KT = K >> 4;   // BK = 16

    auto load_stage = [&](int kb, int buf) {
        const int k0 = kb * 16;
#pragma unroll
        for (int s = 0; s < 2; s++) {
            int j   = t + s * 256;       // 0..511
            int row = j >> 2;
            int c4  = (j & 3) * 4;
            cp16(&As[buf][row][c4], A + (size_t)(bm + row) * K + k0 + c4);
            cp16(&Bs[buf][row][c4], W + (size_t)(bn + row) * K + k0 + c4);
        }
    };

    load_stage(0, 0);
    cp_commit();

    for (int kb = 0; kb < KT; kb++) {
        const int buf = kb & 1;
        if (kb + 1 < KT) {
            load_stage(kb + 1, buf ^ 1);
            cp_commit();
            cp_wait<1>();
        } else {
            cp_wait<0>();
        }
        __syncthreads();

#pragma unroll
        for (int ks = 0; ks < 2; ks++) {
            const int k0 = ks * 8;
            uint32_t bf[4][2];
#pragma unroll
            for (int nt = 0; nt < 4; nt++) {
                bf[nt][0] = cvt_tf32(Bs[buf][wn + nt * 8 + g][k0 + t4]);
                bf[nt][1] = cvt_tf32(Bs[buf][wn + nt * 8 + g][k0 + t4 + 4]);
            }
#pragma unroll
            for (int mt = 0; mt < 4; mt++) {
                uint32_t a0 = cvt_tf32(As[buf][wm + mt * 16 + g][k0 + t4]);
                uint32_t a1 = cvt_tf32(As[buf][wm + mt * 16 + g + 8][k0 + t4]);
                uint32_t a2 = cvt_tf32(As[buf][wm + mt * 16 + g][k0 + t4 + 4]);
                uint32_t a3 = cvt_tf32(As[buf][wm + mt * 16 + g + 8][k0 + t4 + 4]);
#pragma unroll
                for (int nt = 0; nt < 4; nt++)
                    mma_tf32(acc[mt][nt], a0, a1, a2, a3, bf[nt][0], bf[nt][1]);
            }
        }
        __syncthreads();
    }

    // epilogue
#pragma unroll
    for (int mt = 0; mt < 4; mt++) {
#pragma unroll
        for (int nt = 0; nt < 4; nt++) {
            int m = bm + wm + mt * 16 + g;
            int n = bn + wn + nt * 8 + t4 * 2;
            float2 v0 = make_float2(acc[mt][nt][0], acc[mt][nt][1]);
            float2 v1 = make_float2(acc[mt][nt][2], acc[mt][nt][3]);
            if (ACT == 1) {
                v0.x = v0.x / (1.f + __expf(-v0.x));
                v0.y = v0.y / (1.f + __expf(-v0.y));
                v1.x = v1.x / (1.f + __expf(-v1.x));
                v1.y = v1.y / (1.f + __expf(-v1.y));
            }
            *(float2*)&C[(size_t)m * N + n]       = v0;
            *(float2*)&C[(size_t)(m + 8) * N + n] = v1;
        }
    }
}

// ---------------------------------------------------------------------------
// lr/wd chunk means (unchanged)
// ---------------------------------------------------------------------------
__global__ __launch_bounds__(256, 2)
void lrwd_kernel(const float* __restrict__ x,
                 const float* __restrict__ Wlr,
                 const float* __restrict__ Wbeta)
{
    __shared__ float xs[64][65];
    __shared__ float ws[64][65];
    __shared__ float red2[64 * 16];

    const int bc = blockIdx.x;
    const size_t xb = (size_t)bc * 64 * 1024;
    const int t  = threadIdx.x;
    const int r0 = t >> 4;
    const int c0 = t & 15;

    float acc[4][4];
#pragma unroll
    for (int i = 0; i < 4; i++)
#pragma unroll
        for (int j = 0; j < 4; j++) acc[i][j] = 0.f;

    for (int k0 = 0; k0 < 1024; k0 += 64) {
        for (int i = t; i < 4096; i += 256) {
            int n = i >> 6, d = i & 63;
            xs[n][d] = x[xb + (size_t)n * 1024 + k0 + d];
            ws[n][d] = (n < 32) ? Wlr[n * 1024 + k0 + d]
                                : Wbeta[(n - 32) * 1024 + k0 + d];
        }
        __syncthreads();
#pragma unroll 4
        for (int k = 0; k < 64; k++) {
            float a[4], b[4];
#pragma unroll
            for (int ii = 0; ii < 4; ii++) a[ii] = xs[r0 + 16 * ii][k];
#pragma unroll
            for (int jj = 0; jj < 4; jj++) b[jj] = ws[c0 + 16 * jj][k];
#pragma unroll
            for (int ii = 0; ii < 4; ii++)
#pragma unroll
                for (int jj = 0; jj < 4; jj++) acc[ii][jj] += a[ii] * b[jj];
        }
        __syncthreads();
    }

#pragma unroll
    for (int jj = 0; jj < 4; jj++) {
        int j = c0 + 16 * jj;
        float scale = (j < 32) ? 0.001f : 0.9f;
        float p = 0.f;
#pragma unroll
        for (int ii = 0; ii < 4; ii++)
            p += scale / (1.f + __expf(-acc[ii][jj]));
        red2[j * 16 + r0] = p;
    }
    __syncthreads();
    if (t < 64) {
        float s = 0.f;
        for (int r = 0; r < 16; r++) s += red2[t * 16 + r];
        g_lrwd[bc * 64 + t] = s * (1.f / 64.f);
    }
}

// ---------------------------------------------------------------------------
// Persistent scan (unchanged this round)
// ---------------------------------------------------------------------------
#define PAD 65

__global__ __launch_bounds__(256, 1)
void scan_kernel(const float* __restrict__ Win0, const float* __restrict__ Wout0)
{
    extern __shared__ float sm[];
    float* Wi  = sm;
    float* Wo_ = sm + 64 * PAD;
    float* QK  = sm + 2 * 64 * PAD;
    float* Vv  = sm + 3 * 64 * PAD;
    float* Pm  = sm + 4 * 64 * PAD;
    float* Am  = sm + 5 * 64 * PAD;
    float* red = sm + 6 * 64 * PAD;
    float* cs  = red + 256;
    float* sv  = cs + 64;

    const int b = blockIdx.x >> 4;
    const int h = blockIdx.x & 15;
    const int t = threadIdx.x;
    const int r0 = t >> 4;
    const int c0 = t & 15;

    for (int i = t; i < 4096; i += 256) {
        int D = i >> 6, d = i & 63;
        Wi [D * PAD + d] = Win0 [D * 1024 + h * 64 + d];
        Wo_[D * PAD + d] = Wout0[D * 1024 + h * 64 + d];
    }
    __syncthreads();

    for (int c = 0; c < NCHUNK_; c++) {
        const size_t base = ((size_t)b * L_ + (size_t)c * 64) * 1024 + h * 64;
        const int lb = (b * 64 + c) * 64;
        const float li  = g_lrwd[lb + h];
        const float lo  = g_lrwd[lb + 16 + h];
        const float wdi = g_lrwd[lb + 32 + h];
        const float wdo = g_lrwd[lb + 48 + h];

        for (int i = t; i < 4096; i += 256) {
            int n = i >> 6, d = i & 63;
            QK[n * PAD + d] = g_q[base + (size_t)n * 1024 + d];
            Vv[n * PAD + d] = g_v[base + (size_t)n * 1024 + d];
        }
        __syncthreads();

        // logits_q (NT)
        {
            float acc[4][4];
#pragma unroll
            for (int ii = 0; ii < 4; ii++)
#pragma unroll
                for (int jj = 0; jj < 4; jj++) acc[ii][jj] = 0.f;
#pragma unroll 4
            for (int k = 0; k < 64; k++) {
                float a[4], bb[4];
#pragma unroll
                for (int ii = 0; ii < 4; ii++) a[ii]  = QK[(r0 + 16 * ii) * PAD + k];
#pragma unroll
                for (int jj = 0; jj < 4; jj++) bb[jj] = Wi[(c0 + 16 * jj) * PAD + k];
#pragma unroll
                for (int ii = 0; ii < 4; ii++)
#pragma unroll
                    for (int jj = 0; jj < 4; jj++) acc[ii][jj] += a[ii] * bb[jj];
            }
#pragma unroll
            for (int ii = 0; ii < 4; ii++)
#pragma unroll
                for (int jj = 0; jj < 4; jj++)
                    Pm[(r0 + 16 * ii) * PAD + c0 + 16 * jj] = acc[ii][jj];
        }
        __syncthreads();

        // softmax pass 1
        {
            int q = t >> 6, D = t & 63;
            float m = -1e30f;
            for (int n = q * 16; n < q * 16 + 16; n++) m = fmaxf(m, Pm[n * PAD + D]);
            red[q * 64 + D] = m;
        }
        __syncthreads();
        if (t < 64)
            cs[t] = fmaxf(fmaxf(red[t], red[64 + t]), fmaxf(red[128 + t], red[192 + t]));
        __syncthreads();
        {
            int q = t >> 6, D = t & 63;
            float m = cs[D], s = 0.f;
            for (int n = q * 16; n < q * 16 + 16; n++) {
                float e = __expf(Pm[n * PAD + D] - m);
                Pm[n * PAD + D] = e;
                s += e;
            }
            red[q * 64 + D] = s;
        }
        __syncthreads();
        if (t < 64) cs[t] = 1.f / (red[t] + red[64 + t] + red[128 + t] + red[192 + t]);
        __syncthreads();
        {
            int q = t >> 6, D = t & 63;
            float inv = cs[D];
            for (int n = q * 16; n < q * 16 + 16; n++) Pm[n * PAD + D] *= inv;
        }
        __syncthreads();

        // o = p_q @ W_out (NN)
        {
            float acc[4][4];
#pragma unroll
            for (int ii = 0; ii < 4; ii++)
#pragma unroll
                for (int jj = 0; jj < 4; jj++) acc[ii][jj] = 0.f;
#pragma unroll 4
            for (int k = 0; k < 64; k++) {
                float a[4], bb[4];
#pragma unroll
                for (int ii = 0; ii < 4; ii++) a[ii]  = Pm[(r0 + 16 * ii) * PAD + k];
#pragma unroll
                for (int jj = 0; jj < 4; jj++) bb[jj] = Wo_[k * PAD + c0 + 16 * jj];
#pragma unroll
                for (int ii = 0; ii < 4; ii++)
#pragma unroll
                    for (int jj = 0; jj < 4; jj++) acc[ii][jj] += a[ii] * bb[jj];
            }
#pragma unroll
            for (int ii = 0; ii < 4; ii++)
#pragma unroll
                for (int jj = 0; jj < 4; jj++)
                    g_o[base + (size_t)(r0 + 16 * ii) * 1024 + c0 + 16 * jj] = acc[ii][jj];
        }

        // load k tile
        for (int i = t; i < 4096; i += 256) {
            int n = i >> 6, d = i & 63;
            QK[n * PAD + d] = g_k[base + (size_t)n * 1024 + d];
        }
        __syncthreads();

        // logits_k (NT)
        {
            float acc[4][4];
#pragma unroll
            for (int ii = 0; ii < 4; ii++)
#pragma unroll
                for (int jj = 0; jj < 4; jj++) acc[ii][jj] = 0.f;
#pragma unroll 4
            for (int k = 0; k < 64; k++) {
                float a[4], bb[4];
#pragma unroll
                for (int ii = 0; ii < 4; ii++) a[ii]  = QK[(r0 + 16 * ii) * PAD + k];
#pragma unroll
                for (int jj = 0; jj < 4; jj++) bb[jj] = Wi[(c0 + 16 * jj) * PAD + k];
#pragma unroll
                for (int ii = 0; ii < 4; ii++)
#pragma unroll
                    for (int jj = 0; jj < 4; jj++) acc[ii][jj] += a[ii] * bb[jj];
            }
#pragma unroll
            for (int ii = 0; ii < 4; ii++)
#pragma unroll
                for (int jj = 0; jj < 4; jj++)
                    Pm[(r0 + 16 * ii) * PAD + c0 + 16 * jj] = acc[ii][jj];
        }
        __syncthreads();

        // softmax pass 2
        {
            int q = t >> 6, D = t & 63;
            float m = -1e30f;
            for (int n = q * 16; n < q * 16 + 16; n++) m = fmaxf(m, Pm[n * PAD + D]);
            red[q * 64 + D] = m;
        }
        __syncthreads();
        if (t < 64)
            cs[t] = fmaxf(fmaxf(red[t], red[64 + t]), fmaxf(red[128 + t], red[192 + t]));
        __syncthreads();
        {
            int q = t >> 6, D = t & 63;
            float m = cs[D], s = 0.f;
            for (int n = q * 16; n < q * 16 + 16; n++) {
                float e = __expf(Pm[n * PAD + D] - m);
                Pm[n * PAD + D] = e;
                s += e;
            }
            red[q * 64 + D] = s;
        }
        __syncthreads();
        if (t < 64) cs[t] = 1.f / (red[t] + red[64 + t] + red[128 + t] + red[192 + t]);
        __syncthreads();
        {
            int q = t >> 6, D = t & 63;
            float inv = cs[D];
            for (int n = q * 16; n < q * 16 + 16; n++) Pm[n * PAD + D] *= inv;
        }
        __syncthreads();

        // a = v @ W_out^T (NT)
        {
            float acc[4][4];
#pragma unroll
            for (int ii = 0; ii < 4; ii++)
#pragma unroll
                for (int jj = 0; jj < 4; jj++) acc[ii][jj] = 0.f;
#pragma unroll 4
            for (int k = 0; k < 64; k++) {
                float a[4], bb[4];
#pragma unroll
                for (int ii = 0; ii < 4; ii++) a[ii]  = Vv[(r0 + 16 * ii) * PAD + k];
#pragma unroll
                for (int jj = 0; jj < 4; jj++) bb[jj] = Wo_[(c0 + 16 * jj) * PAD + k];
#pragma unroll
                for (int ii = 0; ii < 4; ii++)
#pragma unroll
                    for (int jj = 0; jj < 4; jj++) acc[ii][jj] += a[ii] * bb[jj];
            }
#pragma unroll
            for (int ii = 0; ii < 4; ii++)
#pragma unroll
                for (int jj = 0; jj < 4; jj++)
                    Am[(r0 + 16 * ii) * PAD + c0 + 16 * jj] = acc[ii][jj];
        }
        __syncthreads();

        // s and g_z
        if (t < 64) {
            float s = 0.f;
            for (int D = 0; D < 64; D++) s += Pm[t * PAD + D] * Am[t * PAD + D];
            sv[t] = s;
        }
        __syncthreads();
        for (int i = t; i < 4096; i += 256) {
            int n = i >> 6, D = i & 63;
            Am[n * PAD + D] = -Pm[n * PAD + D] * (Am[n * PAD + D] - sv[n]);
        }
        __syncthreads();

        // fused updates (TN)
        {
            float gin[4][4], gout[4][4];
#pragma unroll
            for (int ii = 0; ii < 4; ii++)
#pragma unroll
                for (int jj = 0; jj < 4; jj++) { gin[ii][jj] = 0.f; gout[ii][jj] = 0.f; }
#pragma unroll 4
            for (int n = 0; n < 64; n++) {
                float gz[4], pp[4], kk[4], vv[4];
#pragma unroll
                for (int ii = 0; ii < 4; ii++) {
                    gz[ii] = Am[n * PAD + r0 + 16 * ii];
                    pp[ii] = Pm[n * PAD + r0 + 16 * ii];
                }
#pragma unroll
                for (int jj = 0; jj < 4; jj++) {
                    kk[jj] = QK[n * PAD + c0 + 16 * jj];
                    vv[jj] = Vv[n * PAD + c0 + 16 * jj];
                }
#pragma unroll
                for (int ii = 0; ii < 4; ii++)
#pragma unroll
                    for (int jj = 0; jj < 4; jj++) {
                        gin[ii][jj]  += gz[ii] * kk[jj];
                        gout[ii][jj] += pp[ii] * vv[jj];
                    }
            }
#pragma unroll
            for (int ii = 0; ii < 4; ii++)
#pragma unroll
                for (int jj = 0; jj < 4; jj++) {
                    int idx = (r0 + 16 * ii) * PAD + c0 + 16 * jj;
                    Wi [idx] = wdi * Wi [idx] - li * gin[ii][jj];
                    Wo_[idx] = wdo * Wo_[idx] + lo * gout[ii][jj];
                }
        }
        __syncthreads();
    }
}

// ---------------------------------------------------------------------------
// Launch
// ---------------------------------------------------------------------------
extern "C" void kernel_launch(void* const* d_in, const int* in_sizes, int n_in,
                              void* d_out, int out_size)
{
    (void)in_sizes; (void)n_in; (void)out_size;
    const float* x     = (const float*)d_in[0];
    const float* Wq    = (const float*)d_in[1];
    const float* Wk    = (const float*)d_in[2];
    const float* Wv    = (const float*)d_in[3];
    const float* Wlr   = (const float*)d_in[4];
    const float* Wbeta = (const float*)d_in[5];
    const float* Wo    = (const float*)d_in[6];
    const float* Win0  = (const float*)d_in[7];
    const float* Wout0 = (const float*)d_in[8];
    float* out = (float*)d_out;

    float *q, *k, *v, *om;
    cudaGetSymbolAddress((void**)&q,  g_q);
    cudaGetSymbolAddress((void**)&k,  g_k);
    cudaGetSymbolAddress((void**)&v,  g_v);
    cudaGetSymbolAddress((void**)&om, g_o);

    dim3 grid(1024 / 128, M_ / 128);
    gemm_tf32<1><<<grid, 256>>>(x, Wq, q, M_, 1024, 1024);
    gemm_tf32<1><<<grid, 256>>>(x, Wk, k, M_, 1024, 1024);
    gemm_tf32<0><<<grid, 256>>>(x, Wv, v, M_, 1024, 1024);
    lrwd_kernel<<<B_ * NCHUNK_, 256>>>(x, Wlr, Wbeta);

    const int smem_bytes = (6 * 64 * PAD + 256 + 64 + 64) * (int)sizeof(float);
    cudaFuncSetAttribute(scan_kernel, cudaFuncAttributeMaxDynamicSharedMemorySize, smem_bytes);
    scan_kernel<<<64, 256, smem_bytes>>>(Win0, Wout0);

    gemm_tf32<0><<<grid, 256>>>(om, Wo, out, M_, 1024, 1024);
}

// round 4
// speedup vs baseline: 2.0351x; 1.1145x over previous
#include <cuda_runtime.h>
#include <cstdint>

// Problem constants
#define B_ 4
#define L_ 4096
#define DIM_ 1024
#define H_ 16
#define NCHUNK_ 64
#define CHUNK_ 64
#define M_ (B_ * L_)          // 16384

// ---------------------------------------------------------------------------
// Device scratch (allocation-free contract: __device__ globals)
// ---------------------------------------------------------------------------
__device__ float g_q[(size_t)B_ * L_ * 1024];
__device__ float g_k[(size_t)B_ * L_ * 1024];
__device__ float g_v[(size_t)B_ * L_ * 1024];
__device__ float g_o[(size_t)B_ * L_ * 1024];
__device__ float g_lrwd[B_ * NCHUNK_ * 64];

// ---------------------------------------------------------------------------
// PTX helpers
// ---------------------------------------------------------------------------
__device__ __forceinline__ uint32_t cvt_tf32(float f) {
    uint32_t u;
    asm("cvt.rna.tf32.f32 %0, %1;" : "=r"(u) : "f"(f));
    return u;
}

__device__ __forceinline__ void cp16(void* smem, const void* gmem) {
    uint32_t s = (uint32_t)__cvta_generic_to_shared(smem);
    asm volatile("cp.async.cg.shared.global [%0], [%1], 16;" :: "r"(s), "l"(gmem));
}
__device__ __forceinline__ void cp_commit() {
    asm volatile("cp.async.commit_group;");
}
template <int N>
__device__ __forceinline__ void cp_wait() {
    asm volatile("cp.async.wait_group %0;" :: "n"(N));
}

__device__ __forceinline__ void mma_tf32(float c[4],
                                         uint32_t a0, uint32_t a1, uint32_t a2, uint32_t a3,
                                         uint32_t b0, uint32_t b1) {
    asm volatile(
        "mma.sync.aligned.m16n8k8.row.col.f32.tf32.tf32.f32 "
        "{%0,%1,%2,%3}, {%4,%5,%6,%7}, {%8,%9}, {%0,%1,%2,%3};"
        : "+f"(c[0]), "+f"(c[1]), "+f"(c[2]), "+f"(c[3])
        : "r"(a0), "r"(a1), "r"(a2), "r"(a3), "r"(b0), "r"(b1));
}

__device__ __forceinline__ uint32_t mapa_u32(uint32_t addr, uint32_t rank) {
    uint32_t r;
    asm("mapa.shared::cluster.u32 %0, %1, %2;" : "=r"(r) : "r"(addr), "r"(rank));
    return r;
}
__device__ __forceinline__ float ld_dsmem(uint32_t addr) {
    float v;
    asm volatile("ld.shared::cluster.f32 %0, [%1];" : "=f"(v) : "r"(addr));
    return v;
}
#define CLUSTER_SYNC() do { \
    asm volatile("barrier.cluster.arrive.aligned;" ::: "memory"); \
    asm volatile("barrier.cluster.wait.aligned;" ::: "memory"); } while (0)

// ---------------------------------------------------------------------------
// TF32 tensor-core GEMM (NT): C[M,N] = A[M,K] @ W[N,K]^T, optional SiLU.
// (unchanged from round 3 — passed at ~137 TF/s)
// ---------------------------------------------------------------------------
template <int ACT>
__global__ __launch_bounds__(256)
void gemm_tf32(const float* __restrict__ A, const float* __restrict__ W,
               float* __restrict__ C, int M, int N, int K)
{
    __shared__ __align__(16) float As[2][128][20];
    __shared__ __align__(16) float Bs[2][128][20];

    const int t    = threadIdx.x;
    const int bm   = blockIdx.y * 128;
    const int bn   = blockIdx.x * 128;
    const int w    = t >> 5;
    const int lane = t & 31;
    const int wm   = (w >> 2) * 64;
    const int wn   = (w & 3) * 32;
    const int g    = lane >> 2;
    const int t4   = lane & 3;

    float acc[4][4][4];
#pragma unroll
    for (int mt = 0; mt < 4; mt++)
#pragma unroll
        for (int nt = 0; nt < 4; nt++)
#pragma unroll
            for (int c = 0; c < 4; c++) acc[mt][nt][c] = 0.f;

    const int KT = K >> 4;

    auto load_stage = [&](int kb, int buf) {
        const int k0 = kb * 16;
#pragma unroll
        for (int s = 0; s < 2; s++) {
            int j   = t + s * 256;
            int row = j >> 2;
            int c4  = (j & 3) * 4;
            cp16(&As[buf][row][c4], A + (size_t)(bm + row) * K + k0 + c4);
            cp16(&Bs[buf][row][c4], W + (size_t)(bn + row) * K + k0 + c4);
        }
    };

    load_stage(0, 0);
    cp_commit();

    for (int kb = 0; kb < KT; kb++) {
        const int buf = kb & 1;
        if (kb + 1 < KT) {
            load_stage(kb + 1, buf ^ 1);
            cp_commit();
            cp_wait<1>();
        } else {
            cp_wait<0>();
        }
        __syncthreads();

#pragma unroll
        for (int ks = 0; ks < 2; ks++) {
            const int k0 = ks * 8;
            uint32_t bf[4][2];
#pragma unroll
            for (int nt = 0; nt < 4; nt++) {
                bf[nt][0] = cvt_tf32(Bs[buf][wn + nt * 8 + g][k0 + t4]);
                bf[nt][1] = cvt_tf32(Bs[buf][wn + nt * 8 + g][k0 + t4 + 4]);
            }
#pragma unroll
            for (int mt = 0; mt < 4; mt++) {
                uint32_t a0 = cvt_tf32(As[buf][wm + mt * 16 + g][k0 + t4]);
                uint32_t a1 = cvt_tf32(As[buf][wm + mt * 16 + g + 8][k0 + t4]);
                uint32_t a2 = cvt_tf32(As[buf][wm + mt * 16 + g][k0 + t4 + 4]);
                uint32_t a3 = cvt_tf32(As[buf][wm + mt * 16 + g + 8][k0 + t4 + 4]);
#pragma unroll
                for (int nt = 0; nt < 4; nt++)
                    mma_tf32(acc[mt][nt], a0, a1, a2, a3, bf[nt][0], bf[nt][1]);
            }
        }
        __syncthreads();
    }

#pragma unroll
    for (int mt = 0; mt < 4; mt++) {
#pragma unroll
        for (int nt = 0; nt < 4; nt++) {
            int m = bm + wm + mt * 16 + g;
            int n = bn + wn + nt * 8 + t4 * 2;
            float2 v0 = make_float2(acc[mt][nt][0], acc[mt][nt][1]);
            float2 v1 = make_float2(acc[mt][nt][2], acc[mt][nt][3]);
            if (ACT == 1) {
                v0.x = v0.x / (1.f + __expf(-v0.x));
                v0.y = v0.y / (1.f + __expf(-v0.y));
                v1.x = v1.x / (1.f + __expf(-v1.x));
                v1.y = v1.y / (1.f + __expf(-v1.y));
            }
            *(float2*)&C[(size_t)m * N + n]       = v0;
            *(float2*)&C[(size_t)(m + 8) * N + n] = v1;
        }
    }
}

// ---------------------------------------------------------------------------
// lr/wd chunk means (unchanged)
// ---------------------------------------------------------------------------
__global__ __launch_bounds__(256, 2)
void lrwd_kernel(const float* __restrict__ x,
                 const float* __restrict__ Wlr,
                 const float* __restrict__ Wbeta)
{
    __shared__ float xs[64][65];
    __shared__ float ws[64][65];
    __shared__ float red2[64 * 16];

    const int bc = blockIdx.x;
    const size_t xb = (size_t)bc * 64 * 1024;
    const int t  = threadIdx.x;
    const int r0 = t >> 4;
    const int c0 = t & 15;

    float acc[4][4];
#pragma unroll
    for (int i = 0; i < 4; i++)
#pragma unroll
        for (int j = 0; j < 4; j++) acc[i][j] = 0.f;

    for (int k0 = 0; k0 < 1024; k0 += 64) {
        for (int i = t; i < 4096; i += 256) {
            int n = i >> 6, d = i & 63;
            xs[n][d] = x[xb + (size_t)n * 1024 + k0 + d];
            ws[n][d] = (n < 32) ? Wlr[n * 1024 + k0 + d]
                                : Wbeta[(n - 32) * 1024 + k0 + d];
        }
        __syncthreads();
#pragma unroll 4
        for (int k = 0; k < 64; k++) {
            float a[4], b[4];
#pragma unroll
            for (int ii = 0; ii < 4; ii++) a[ii] = xs[r0 + 16 * ii][k];
#pragma unroll
            for (int jj = 0; jj < 4; jj++) b[jj] = ws[c0 + 16 * jj][k];
#pragma unroll
            for (int ii = 0; ii < 4; ii++)
#pragma unroll
                for (int jj = 0; jj < 4; jj++) acc[ii][jj] += a[ii] * b[jj];
        }
        __syncthreads();
    }

#pragma unroll
    for (int jj = 0; jj < 4; jj++) {
        int j = c0 + 16 * jj;
        float scale = (j < 32) ? 0.001f : 0.9f;
        float p = 0.f;
#pragma unroll
        for (int ii = 0; ii < 4; ii++)
            p += scale / (1.f + __expf(-acc[ii][jj]));
        red2[j * 16 + r0] = p;
    }
    __syncthreads();
    if (t < 64) {
        float s = 0.f;
        for (int r = 0; r < 16; r++) s += red2[t * 16 + r];
        g_lrwd[bc * 64 + t] = s * (1.f / 64.f);
    }
}

// ---------------------------------------------------------------------------
// Cluster-2 persistent scan: each (b,h) pair split across 2 CTAs along D.
// CTA rank r owns D in [r*32, r*32+32). Softmax is column-wise (per-D) =>
// fully local. Cross-CTA: partial o (DSMEM 8KB) and s[n] (64 floats).
// ---------------------------------------------------------------------------
#define P64 65
#define P32 33

#define OFF_WI  0
#define OFF_WO  (32 * P64)                 // 2080
#define OFF_QK  (2 * 32 * P64)             // 4160
#define OFF_VV  (OFF_QK + 64 * P64)        // 8320
#define OFF_PM  (OFF_VV + 64 * P64)        // 12480
#define OFF_AM  (OFF_PM + 64 * P32)        // 14592
#define OFF_OP  (OFF_AM + 64 * P32)        // 16704
#define OFF_SP  (OFF_OP + 64 * P64)        // 20864
#define OFF_SS  (OFF_SP + 64)              // 20928
#define OFF_RED (OFF_SS + 64)              // 20992
#define OFF_CS  (OFF_RED + 256)            // 21248
#define SCAN_SMEM_FLOATS (OFF_CS + 32)     // 21280

__global__ __launch_bounds__(256, 1) __cluster_dims__(2, 1, 1)
void scan_kernel(const float* __restrict__ Win0, const float* __restrict__ Wout0)
{
    extern __shared__ float sm[];
    float* Wi  = sm + OFF_WI;    // [32][P64]  W_in rows (this CTA's D-half)
    float* Wo_ = sm + OFF_WO;    // [32][P64]  W_out rows
    float* QK  = sm + OFF_QK;    // [64][P64]  q then k tile
    float* Vv  = sm + OFF_VV;    // [64][P64]  v tile
    float* Pm  = sm + OFF_PM;    // [64][P32]  probs (D-half)
    float* Am  = sm + OFF_AM;    // [64][P32]  a then g_z
    float* op  = sm + OFF_OP;    // [64][P64]  partial o
    float* sp  = sm + OFF_SP;    // [64]       partial s
    float* ss  = sm + OFF_SS;    // [64]       total s
    float* red = sm + OFF_RED;   // [8][32]
    float* cs  = sm + OFF_CS;    // [32]

    const int pair = blockIdx.x >> 1;
    const uint32_t rank = blockIdx.x & 1;   // cluster ctarank
    const int b = pair >> 4;
    const int h = pair & 15;
    const int t  = threadIdx.x;
    const int r0 = t >> 4;    // 0..15
    const int c0 = t & 15;    // 0..15

    const uint32_t op_peer = mapa_u32((uint32_t)__cvta_generic_to_shared(op), rank ^ 1u);
    const uint32_t sp_peer = mapa_u32((uint32_t)__cvta_generic_to_shared(sp), rank ^ 1u);

    // init state halves; W*_init shape (1, DINNER, H, DQK)
    for (int i = t; i < 2048; i += 256) {
        int Dl = i >> 6, d = i & 63;
        int Dg = (int)rank * 32 + Dl;
        Wi [Dl * P64 + d] = Win0 [Dg * 1024 + h * 64 + d];
        Wo_[Dl * P64 + d] = Wout0[Dg * 1024 + h * 64 + d];
    }
    __syncthreads();

    auto softmax_half = [&]() {
        const int qg = t >> 5, D = t & 31;
        float m = -1e30f;
#pragma unroll
        for (int n = qg * 8; n < qg * 8 + 8; n++) m = fmaxf(m, Pm[n * P32 + D]);
        red[qg * 32 + D] = m;
        __syncthreads();
        if (t < 32) {
            float mm = red[t];
#pragma unroll
            for (int j = 1; j < 8; j++) mm = fmaxf(mm, red[j * 32 + t]);
            cs[t] = mm;
        }
        __syncthreads();
        {
            float mm = cs[D], s = 0.f;
#pragma unroll
            for (int n = qg * 8; n < qg * 8 + 8; n++) {
                float e = __expf(Pm[n * P32 + D] - mm);
                Pm[n * P32 + D] = e;
                s += e;
            }
            red[qg * 32 + D] = s;
        }
        __syncthreads();
        if (t < 32) {
            float s2 = 0.f;
#pragma unroll
            for (int j = 0; j < 8; j++) s2 += red[j * 32 + t];
            cs[t] = 1.f / s2;
        }
        __syncthreads();
        {
            float inv = cs[D];
#pragma unroll
            for (int n = qg * 8; n < qg * 8 + 8; n++) Pm[n * P32 + D] *= inv;
        }
        __syncthreads();
    };

    for (int c = 0; c < NCHUNK_; c++) {
        const size_t base = ((size_t)b * L_ + (size_t)c * 64) * 1024 + h * 64;
        const int lb = (b * 64 + c) * 64;
        const float li  = g_lrwd[lb + h];
        const float lo  = g_lrwd[lb + 16 + h];
        const float wdi = g_lrwd[lb + 32 + h];
        const float wdo = g_lrwd[lb + 48 + h];

        // load q, v tiles (full 64x64, both CTAs)
        for (int i = t; i < 4096; i += 256) {
            int n = i >> 6, d = i & 63;
            QK[n * P64 + d] = g_q[base + (size_t)n * 1024 + d];
            Vv[n * P64 + d] = g_v[base + (size_t)n * 1024 + d];
        }
        __syncthreads();

        // logits_q: Pm[n][Dl] = sum_d q[n][d] * Wi[Dl][d]
        {
            float acc[4][2];
#pragma unroll
            for (int ii = 0; ii < 4; ii++) { acc[ii][0] = 0.f; acc[ii][1] = 0.f; }
#pragma unroll 4
            for (int k = 0; k < 64; k++) {
                float a[4], bb[2];
#pragma unroll
                for (int ii = 0; ii < 4; ii++) a[ii]  = QK[(r0 + 16 * ii) * P64 + k];
#pragma unroll
                for (int jj = 0; jj < 2; jj++) bb[jj] = Wi[(c0 + 16 * jj) * P64 + k];
#pragma unroll
                for (int ii = 0; ii < 4; ii++)
#pragma unroll
                    for (int jj = 0; jj < 2; jj++) acc[ii][jj] += a[ii] * bb[jj];
            }
#pragma unroll
            for (int ii = 0; ii < 4; ii++)
#pragma unroll
                for (int jj = 0; jj < 2; jj++)
                    Pm[(r0 + 16 * ii) * P32 + c0 + 16 * jj] = acc[ii][jj];
        }
        __syncthreads();

        softmax_half();

        // partial o: op[n][d] = sum_{Dl} Pm[n][Dl] * Wo_[Dl][d]
        {
            float acc[4][4];
#pragma unroll
            for (int ii = 0; ii < 4; ii++)
#pragma unroll
                for (int jj = 0; jj < 4; jj++) acc[ii][jj] = 0.f;
#pragma unroll 4
            for (int k = 0; k < 32; k++) {
                float a[4], bb[4];
#pragma unroll
                for (int ii = 0; ii < 4; ii++) a[ii]  = Pm[(r0 + 16 * ii) * P32 + k];
#pragma unroll
                for (int jj = 0; jj < 4; jj++) bb[jj] = Wo_[k * P64 + c0 + 16 * jj];
#pragma unroll
                for (int ii = 0; ii < 4; ii++)
#pragma unroll
                    for (int jj = 0; jj < 4; jj++) acc[ii][jj] += a[ii] * bb[jj];
            }
#pragma unroll
            for (int ii = 0; ii < 4; ii++)
#pragma unroll
                for (int jj = 0; jj < 4; jj++)
                    op[(r0 + 16 * ii) * P64 + c0 + 16 * jj] = acc[ii][jj];
        }
        CLUSTER_SYNC();

        // o = op_self + op_peer; this CTA writes rows [rank*32, rank*32+32)
        for (int i = t; i < 2048; i += 256) {
            int nl = i >> 6, d = i & 63;
            int n = (int)rank * 32 + nl;
            float v2 = op[n * P64 + d] + ld_dsmem(op_peer + (uint32_t)(n * P64 + d) * 4u);
            g_o[base + (size_t)n * 1024 + d] = v2;
        }

        // load k tile
        for (int i = t; i < 4096; i += 256) {
            int n = i >> 6, d = i & 63;
            QK[n * P64 + d] = g_k[base + (size_t)n * 1024 + d];
        }
        __syncthreads();

        // logits_k
        {
            float acc[4][2];
#pragma unroll
            for (int ii = 0; ii < 4; ii++) { acc[ii][0] = 0.f; acc[ii][1] = 0.f; }
#pragma unroll 4
            for (int k = 0; k < 64; k++) {
                float a[4], bb[2];
#pragma unroll
                for (int ii = 0; ii < 4; ii++) a[ii]  = QK[(r0 + 16 * ii) * P64 + k];
#pragma unroll
                for (int jj = 0; jj < 2; jj++) bb[jj] = Wi[(c0 + 16 * jj) * P64 + k];
#pragma unroll
                for (int ii = 0; ii < 4; ii++)
#pragma unroll
                    for (int jj = 0; jj < 2; jj++) acc[ii][jj] += a[ii] * bb[jj];
            }
#pragma unroll
            for (int ii = 0; ii < 4; ii++)
#pragma unroll
                for (int jj = 0; jj < 2; jj++)
                    Pm[(r0 + 16 * ii) * P32 + c0 + 16 * jj] = acc[ii][jj];
        }
        __syncthreads();

        softmax_half();

        // a[n][Dl] = sum_d v[n][d] * Wo_[Dl][d]
        {
            float acc[4][2];
#pragma unroll
            for (int ii = 0; ii < 4; ii++) { acc[ii][0] = 0.f; acc[ii][1] = 0.f; }
#pragma unroll 4
            for (int k = 0; k < 64; k++) {
                float a[4], bb[2];
#pragma unroll
                for (int ii = 0; ii < 4; ii++) a[ii]  = Vv[(r0 + 16 * ii) * P64 + k];
#pragma unroll
                for (int jj = 0; jj < 2; jj++) bb[jj] = Wo_[(c0 + 16 * jj) * P64 + k];
#pragma unroll
                for (int ii = 0; ii < 4; ii++)
#pragma unroll
                    for (int jj = 0; jj < 2; jj++) acc[ii][jj] += a[ii] * bb[jj];
            }
#pragma unroll
            for (int ii = 0; ii < 4; ii++)
#pragma unroll
                for (int jj = 0; jj < 2; jj++)
                    Am[(r0 + 16 * ii) * P32 + c0 + 16 * jj] = acc[ii][jj];
        }
        __syncthreads();

        // partial s over this D-half
        if (t < 64) {
            float s = 0.f;
#pragma unroll 8
            for (int Dl = 0; Dl < 32; Dl++) s += Pm[t * P32 + Dl] * Am[t * P32 + Dl];
            sp[t] = s;
        }
        __syncthreads();
        CLUSTER_SYNC();
        if (t < 64) ss[t] = sp[t] + ld_dsmem(sp_peer + (uint32_t)t * 4u);
        __syncthreads();

        // g_z into Am
        for (int i = t; i < 2048; i += 256) {
            int n = i >> 5, D = i & 31;
            Am[n * P32 + D] = -Pm[n * P32 + D] * (Am[n * P32 + D] - ss[n]);
        }
        __syncthreads();

        // fused grads + state update (local, rows = this CTA's D-half)
        {
            float gin[2][4], gout[2][4];
#pragma unroll
            for (int ii = 0; ii < 2; ii++)
#pragma unroll
                for (int jj = 0; jj < 4; jj++) { gin[ii][jj] = 0.f; gout[ii][jj] = 0.f; }
#pragma unroll 4
            for (int n = 0; n < 64; n++) {
                float gz[2], pp[2], kk[4], vv[4];
#pragma unroll
                for (int ii = 0; ii < 2; ii++) {
                    gz[ii] = Am[n * P32 + r0 + 16 * ii];
                    pp[ii] = Pm[n * P32 + r0 + 16 * ii];
                }
#pragma unroll
                for (int jj = 0; jj < 4; jj++) {
                    kk[jj] = QK[n * P64 + c0 + 16 * jj];
                    vv[jj] = Vv[n * P64 + c0 + 16 * jj];
                }
#pragma unroll
                for (int ii = 0; ii < 2; ii++)
#pragma unroll
                    for (int jj = 0; jj < 4; jj++) {
                        gin[ii][jj]  += gz[ii] * kk[jj];
                        gout[ii][jj] += pp[ii] * vv[jj];
                    }
            }
#pragma unroll
            for (int ii = 0; ii < 2; ii++)
#pragma unroll
                for (int jj = 0; jj < 4; jj++) {
                    int idx = (r0 + 16 * ii) * P64 + c0 + 16 * jj;
                    Wi [idx] = wdi * Wi [idx] - li * gin[ii][jj];
                    Wo_[idx] = wdo * Wo_[idx] + lo * gout[ii][jj];
                }
        }
        __syncthreads();
    }
    CLUSTER_SYNC();   // keep smem alive until peer's last DSMEM reads are done
}

// ---------------------------------------------------------------------------
// Launch
// ---------------------------------------------------------------------------
extern "C" void kernel_launch(void* const* d_in, const int* in_sizes, int n_in,
                              void* d_out, int out_size)
{
    (void)in_sizes; (void)n_in; (void)out_size;
    const float* x     = (const float*)d_in[0];
    const float* Wq    = (const float*)d_in[1];
    const float* Wk    = (const float*)d_in[2];
    const float* Wv    = (const float*)d_in[3];
    const float* Wlr   = (const float*)d_in[4];
    const float* Wbeta = (const float*)d_in[5];
    const float* Wo    = (const float*)d_in[6];
    const float* Win0  = (const float*)d_in[7];
    const float* Wout0 = (const float*)d_in[8];
    float* out = (float*)d_out;

    float *q, *k, *v, *om;
    cudaGetSymbolAddress((void**)&q,  g_q);
    cudaGetSymbolAddress((void**)&k,  g_k);
    cudaGetSymbolAddress((void**)&v,  g_v);
    cudaGetSymbolAddress((void**)&om, g_o);

    dim3 grid(1024 / 128, M_ / 128);
    gemm_tf32<1><<<grid, 256>>>(x, Wq, q, M_, 1024, 1024);
    gemm_tf32<1><<<grid, 256>>>(x, Wk, k, M_, 1024, 1024);
    gemm_tf32<0><<<grid, 256>>>(x, Wv, v, M_, 1024, 1024);
    lrwd_kernel<<<B_ * NCHUNK_, 256>>>(x, Wlr, Wbeta);

    const int smem_bytes = SCAN_SMEM_FLOATS * (int)sizeof(float);
    cudaFuncSetAttribute(scan_kernel, cudaFuncAttributeMaxDynamicSharedMemorySize, smem_bytes);
    scan_kernel<<<128, 256, smem_bytes>>>(Win0, Wout0);

    gemm_tf32<0><<<grid, 256>>>(om, Wo, out, M_, 1024, 1024);
}

// round 7
// speedup vs baseline: 2.4157x; 1.1870x over previous
#include <cuda_runtime.h>
#include <cstdint>

// Problem constants
#define B_ 4
#define L_ 4096
#define DIM_ 1024
#define H_ 16
#define NCHUNK_ 64
#define CHUNK_ 64
#define M_ (B_ * L_)          // 16384

// ---------------------------------------------------------------------------
// Device scratch (allocation-free contract: __device__ globals)
// ---------------------------------------------------------------------------
__device__ float g_q[(size_t)B_ * L_ * 1024];
__device__ float g_k[(size_t)B_ * L_ * 1024];   // reused as tf32(o) before last GEMM
__device__ float g_v[(size_t)B_ * L_ * 1024];
__device__ float g_o[(size_t)B_ * L_ * 1024];
__device__ float g_xt[(size_t)B_ * L_ * 1024];  // tf32(x)
__device__ float g_wt[4u * 1024u * 1024u];      // tf32(Wq,Wk,Wv,Wo)
__device__ float g_lrwd[B_ * NCHUNK_ * 64];

// ---------------------------------------------------------------------------
// PTX helpers
// ---------------------------------------------------------------------------
__device__ __forceinline__ float cvt_tf32f(float f) {
    uint32_t u;
    asm("cvt.rna.tf32.f32 %0, %1;" : "=r"(u) : "f"(f));
    return __uint_as_float(u);
}

__device__ __forceinline__ void cp16(void* smem, const void* gmem) {
    uint32_t s = (uint32_t)__cvta_generic_to_shared(smem);
    asm volatile("cp.async.cg.shared.global [%0], [%1], 16;" :: "r"(s), "l"(gmem));
}
__device__ __forceinline__ void cp_commit() {
    asm volatile("cp.async.commit_group;");
}
template <int N>
__device__ __forceinline__ void cp_wait() {
    asm volatile("cp.async.wait_group %0;" :: "n"(N));
}

__device__ __forceinline__ void mma_tf32(float c[4],
                                         uint32_t a0, uint32_t a1, uint32_t a2, uint32_t a3,
                                         uint32_t b0, uint32_t b1) {
    asm volatile(
        "mma.sync.aligned.m16n8k8.row.col.f32.tf32.tf32.f32 "
        "{%0,%1,%2,%3}, {%4,%5,%6,%7}, {%8,%9}, {%0,%1,%2,%3};"
        : "+f"(c[0]), "+f"(c[1]), "+f"(c[2]), "+f"(c[3])
        : "r"(a0), "r"(a1), "r"(a2), "r"(a3), "r"(b0), "r"(b1));
}

__device__ __forceinline__ uint32_t mapa_u32(uint32_t addr, uint32_t rank) {
    uint32_t r;
    asm("mapa.shared::cluster.u32 %0, %1, %2;" : "=r"(r) : "r"(addr), "r"(rank));
    return r;
}
__device__ __forceinline__ float ld_dsmem(uint32_t addr) {
    float v;
    asm volatile("ld.shared::cluster.f32 %0, [%1];" : "=f"(v) : "r"(addr));
    return v;
}
#define CLUSTER_SYNC() do { \
    asm volatile("barrier.cluster.arrive.aligned;" ::: "memory"); \
    asm volatile("barrier.cluster.wait.aligned;" ::: "memory"); } while (0)

// ---------------------------------------------------------------------------
// tf32 pre-convert: dst[i] = tf32(src[i]) (bit pattern stored as float)
// ---------------------------------------------------------------------------
__global__ __launch_bounds__(256)
void cvt_kernel(const float* __restrict__ src, float* __restrict__ dst, int n4)
{
    int i = blockIdx.x * 256 + threadIdx.x;
    if (i < n4) {
        float4 v = ((const float4*)src)[i];
        v.x = cvt_tf32f(v.x); v.y = cvt_tf32f(v.y);
        v.z = cvt_tf32f(v.z); v.w = cvt_tf32f(v.w);
        ((float4*)dst)[i] = v;
    }
}

// ---------------------------------------------------------------------------
// TF32 tensor-core GEMM (NT), pre-converted inputs, 3-stage cp.async.
// C[M,N] = A[M,K] @ W[N,K]^T, optional SiLU. 128x128 block, BK=16,
// 256 threads, warp tile 64x32 (4x4 m16n8k8). Stage buffers in DYNAMIC smem.
// ---------------------------------------------------------------------------
#define GEMM_SMEM_BYTES (3 * 2 * 128 * 20 * 4)

template <int ACT>
__global__ __launch_bounds__(256)
void gemm_tf32p(const float* __restrict__ A, const float* __restrict__ W,
                float* __restrict__ C, int M, int N, int K)
{
    extern __shared__ __align__(16) float gsm[];
    float (*As)[128][20] = (float (*)[128][20])gsm;
    float (*Bs)[128][20] = (float (*)[128][20])(gsm + 3 * 128 * 20);

    const int t    = threadIdx.x;
    const int bm   = blockIdx.y * 128;
    const int bn   = blockIdx.x * 128;
    const int w    = t >> 5;
    const int lane = t & 31;
    const int wm   = (w >> 2) * 64;
    const int wn   = (w & 3) * 32;
    const int g    = lane >> 2;
    const int t4   = lane & 3;

    float acc[4][4][4];
#pragma unroll
    for (int mt = 0; mt < 4; mt++)
#pragma unroll
        for (int nt = 0; nt < 4; nt++)
#pragma unroll
            for (int c = 0; c < 4; c++) acc[mt][nt][c] = 0.f;

    const int KT = K >> 4;

    auto load_stage = [&](int kb, int buf) {
        const int k0 = kb * 16;
#pragma unroll
        for (int s = 0; s < 2; s++) {
            int j   = t + s * 256;
            int row = j >> 2;
            int c4  = (j & 3) * 4;
            cp16(&As[buf][row][c4], A + (size_t)(bm + row) * K + k0 + c4);
            cp16(&Bs[buf][row][c4], W + (size_t)(bn + row) * K + k0 + c4);
        }
    };

    load_stage(0, 0); cp_commit();
    load_stage(1, 1); cp_commit();

    for (int kb = 0; kb < KT; kb++) {
        cp_wait<1>();
        __syncthreads();
        if (kb + 2 < KT) { load_stage(kb + 2, (kb + 2) % 3); cp_commit(); }
        else             { cp_commit(); }   // empty group keeps wait<1> semantics
        const int buf = kb % 3;

#pragma unroll
        for (int ks = 0; ks < 2; ks++) {
            const int k0 = ks * 8;
            uint32_t bf[4][2];
#pragma unroll
            for (int nt = 0; nt < 4; nt++) {
                bf[nt][0] = __float_as_uint(Bs[buf][wn + nt * 8 + g][k0 + t4]);
                bf[nt][1] = __float_as_uint(Bs[buf][wn + nt * 8 + g][k0 + t4 + 4]);
            }
#pragma unroll
            for (int mt = 0; mt < 4; mt++) {
                uint32_t a0 = __float_as_uint(As[buf][wm + mt * 16 + g][k0 + t4]);
                uint32_t a1 = __float_as_uint(As[buf][wm + mt * 16 + g + 8][k0 + t4]);
                uint32_t a2 = __float_as_uint(As[buf][wm + mt * 16 + g][k0 + t4 + 4]);
                uint32_t a3 = __float_as_uint(As[buf][wm + mt * 16 + g + 8][k0 + t4 + 4]);
#pragma unroll
                for (int nt = 0; nt < 4; nt++)
                    mma_tf32(acc[mt][nt], a0, a1, a2, a3, bf[nt][0], bf[nt][1]);
            }
        }
        __syncthreads();
    }

#pragma unroll
    for (int mt = 0; mt < 4; mt++) {
#pragma unroll
        for (int nt = 0; nt < 4; nt++) {
            int m = bm + wm + mt * 16 + g;
            int n = bn + wn + nt * 8 + t4 * 2;
            float2 v0 = make_float2(acc[mt][nt][0], acc[mt][nt][1]);
            float2 v1 = make_float2(acc[mt][nt][2], acc[mt][nt][3]);
            if (ACT == 1) {
                v0.x = v0.x / (1.f + __expf(-v0.x));
                v0.y = v0.y / (1.f + __expf(-v0.y));
                v1.x = v1.x / (1.f + __expf(-v1.x));
                v1.y = v1.y / (1.f + __expf(-v1.y));
            }
            *(float2*)&C[(size_t)m * N + n]       = v0;
            *(float2*)&C[(size_t)(m + 8) * N + n] = v1;
        }
    }
}

// ---------------------------------------------------------------------------
// lr/wd chunk means
// ---------------------------------------------------------------------------
__global__ __launch_bounds__(256, 2)
void lrwd_kernel(const float* __restrict__ x,
                 const float* __restrict__ Wlr,
                 const float* __restrict__ Wbeta)
{
    __shared__ float xs[64][65];
    __shared__ float ws[64][65];
    __shared__ float red2[64 * 16];

    const int bc = blockIdx.x;
    const size_t xb = (size_t)bc * 64 * 1024;
    const int t  = threadIdx.x;
    const int r0 = t >> 4;
    const int c0 = t & 15;

    float acc[4][4];
#pragma unroll
    for (int i = 0; i < 4; i++)
#pragma unroll
        for (int j = 0; j < 4; j++) acc[i][j] = 0.f;

    for (int k0 = 0; k0 < 1024; k0 += 64) {
        for (int i = t; i < 4096; i += 256) {
            int n = i >> 6, d = i & 63;
            xs[n][d] = x[xb + (size_t)n * 1024 + k0 + d];
            ws[n][d] = (n < 32) ? Wlr[n * 1024 + k0 + d]
                                : Wbeta[(n - 32) * 1024 + k0 + d];
        }
        __syncthreads();
#pragma unroll 4
        for (int k = 0; k < 64; k++) {
            float a[4], b[4];
#pragma unroll
            for (int ii = 0; ii < 4; ii++) a[ii] = xs[r0 + 16 * ii][k];
#pragma unroll
            for (int jj = 0; jj < 4; jj++) b[jj] = ws[c0 + 16 * jj][k];
#pragma unroll
            for (int ii = 0; ii < 4; ii++)
#pragma unroll
                for (int jj = 0; jj < 4; jj++) acc[ii][jj] += a[ii] * b[jj];
        }
        __syncthreads();
    }

#pragma unroll
    for (int jj = 0; jj < 4; jj++) {
        int j = c0 + 16 * jj;
        float scale = (j < 32) ? 0.001f : 0.9f;
        float p = 0.f;
#pragma unroll
        for (int ii = 0; ii < 4; ii++)
            p += scale / (1.f + __expf(-acc[ii][jj]));
        red2[j * 16 + r0] = p;
    }
    __syncthreads();
    if (t < 64) {
        float s = 0.f;
        for (int r = 0; r < 16; r++) s += red2[t * 16 + r];
        g_lrwd[bc * 64 + t] = s * (1.f / 64.f);
    }
}

// ---------------------------------------------------------------------------
// Cluster-2 persistent scan, restructured: 7 phases per chunk.
// ---------------------------------------------------------------------------
#define P64 65
#define P32 33

#define OFF_WI   0                           // [32][65]
#define OFF_WO   (32 * P64)
#define OFF_Q    (2 * 32 * P64)              // [64][65]
#define OFF_K    (OFF_Q + 64 * P64)
#define OFF_V    (OFF_K + 64 * P64)
#define OFF_PQ   (OFF_V + 64 * P64)          // [64][33]
#define OFF_PK   (OFF_PQ + 64 * P32)
#define OFF_AM   (OFF_PK + 64 * P32)
#define OFF_OP   (OFF_AM + 64 * P32)         // [64][65]
#define OFF_SP   (OFF_OP + 64 * P64)
#define OFF_SS   (OFF_SP + 64)
#define OFF_RED  (OFF_SS + 64)               // [4][64]
#define OFF_CS   (OFF_RED + 256)
#define SCAN_SMEM_FLOATS (OFF_CS + 64)       // 27584 floats -> 110336 bytes

__global__ __launch_bounds__(256, 1) __cluster_dims__(2, 1, 1)
void scan_kernel(const float* __restrict__ Win0, const float* __restrict__ Wout0)
{
    extern __shared__ float sm[];
    float* Wi  = sm + OFF_WI;
    float* Wo_ = sm + OFF_WO;
    float* Q   = sm + OFF_Q;
    float* Kt  = sm + OFF_K;
    float* V   = sm + OFF_V;
    float* Pq  = sm + OFF_PQ;
    float* Pk  = sm + OFF_PK;
    float* Am  = sm + OFF_AM;
    float* op  = sm + OFF_OP;
    float* sp  = sm + OFF_SP;
    float* ss  = sm + OFF_SS;
    float* red = sm + OFF_RED;
    float* cs  = sm + OFF_CS;

    const int pair = blockIdx.x >> 1;
    const uint32_t rank = blockIdx.x & 1;
    const int b = pair >> 4;
    const int h = pair & 15;
    const int t = threadIdx.x;

    const int r8  = t >> 3, c8  = t & 7;    // 32x8 grid (logits, a)
    const int r16 = t >> 4, c16 = t & 15;   // 16x16 grid (o)
    const int rg  = t >> 5, cg  = t & 31;   // 8x32 grid (grads)
    const int task = t & 63, sg = t >> 6;   // softmax

    const uint32_t op_peer = mapa_u32((uint32_t)__cvta_generic_to_shared(op), rank ^ 1u);
    const uint32_t sp_peer = mapa_u32((uint32_t)__cvta_generic_to_shared(sp), rank ^ 1u);

    // init state halves
    for (int i = t; i < 2048; i += 256) {
        int Dl = i >> 6, d = i & 63;
        int Dg = (int)rank * 32 + Dl;
        Wi [Dl * P64 + d] = Win0 [Dg * 1024 + h * 64 + d];
        Wo_[Dl * P64 + d] = Wout0[Dg * 1024 + h * 64 + d];
    }
    __syncthreads();

    for (int c = 0; c < NCHUNK_; c++) {
        const size_t base = ((size_t)b * L_ + (size_t)c * 64) * 1024 + h * 64;
        const int lb = (b * 64 + c) * 64;
        const float li  = g_lrwd[lb + h];
        const float lo  = g_lrwd[lb + 16 + h];
        const float wdi = g_lrwd[lb + 32 + h];
        const float wdo = g_lrwd[lb + 48 + h];

        // ---- P1: load q,k,v tiles (float4 LDG)
        for (int i = t; i < 1024; i += 256) {
            int n = i >> 4, d4 = (i & 15) * 4;
            size_t gidx = base + (size_t)n * 1024 + d4;
            float4 a = *(const float4*)&g_q[gidx];
            float4 e = *(const float4*)&g_k[gidx];
            float4 f = *(const float4*)&g_v[gidx];
            Q [n * P64 + d4] = a.x; Q [n * P64 + d4 + 1] = a.y; Q [n * P64 + d4 + 2] = a.z; Q [n * P64 + d4 + 3] = a.w;
            Kt[n * P64 + d4] = e.x; Kt[n * P64 + d4 + 1] = e.y; Kt[n * P64 + d4 + 2] = e.z; Kt[n * P64 + d4 + 3] = e.w;
            V [n * P64 + d4] = f.x; V [n * P64 + d4 + 1] = f.y; V [n * P64 + d4 + 2] = f.z; V [n * P64 + d4 + 3] = f.w;
        }
        __syncthreads();

        // ---- P2: fused q/k logits vs Wi (M=128, N=32, K=64)
        {
            float aq[2][4], ak[2][4];
#pragma unroll
            for (int i = 0; i < 2; i++)
#pragma unroll
                for (int j = 0; j < 4; j++) { aq[i][j] = 0.f; ak[i][j] = 0.f; }
#pragma unroll 4
            for (int k = 0; k < 64; k++) {
                float q0 = Q [r8 * P64 + k],        q1 = Q [(r8 + 32) * P64 + k];
                float k0 = Kt[r8 * P64 + k],        k1 = Kt[(r8 + 32) * P64 + k];
                float bw[4];
#pragma unroll
                for (int j = 0; j < 4; j++) bw[j] = Wi[(c8 + 8 * j) * P64 + k];
#pragma unroll
                for (int j = 0; j < 4; j++) {
                    aq[0][j] += q0 * bw[j];
                    aq[1][j] += q1 * bw[j];
                    ak[0][j] += k0 * bw[j];
                    ak[1][j] += k1 * bw[j];
                }
            }
#pragma unroll
            for (int j = 0; j < 4; j++) {
                Pq[r8 * P32 + c8 + 8 * j]        = aq[0][j];
                Pq[(r8 + 32) * P32 + c8 + 8 * j] = aq[1][j];
                Pk[r8 * P32 + c8 + 8 * j]        = ak[0][j];
                Pk[(r8 + 32) * P32 + c8 + 8 * j] = ak[1][j];
            }
        }
        __syncthreads();

        // ---- P3: merged softmax over n for both Pq and Pk (per column D)
        {
            float* Pp = (task < 32) ? Pq : Pk;
            const int D = task & 31;
            float m = -1e30f;
#pragma unroll
            for (int n = sg * 16; n < sg * 16 + 16; n++) m = fmaxf(m, Pp[n * P32 + D]);
            red[sg * 64 + task] = m;
            __syncthreads();
            if (t < 64)
                cs[t] = fmaxf(fmaxf(red[t], red[64 + t]), fmaxf(red[128 + t], red[192 + t]));
            __syncthreads();
            float mm = cs[task], s = 0.f;
#pragma unroll
            for (int n = sg * 16; n < sg * 16 + 16; n++) {
                float e = __expf(Pp[n * P32 + D] - mm);
                Pp[n * P32 + D] = e;
                s += e;
            }
            red[sg * 64 + task] = s;
            __syncthreads();
            if (t < 64) cs[t] = 1.f / (red[t] + red[64 + t] + red[128 + t] + red[192 + t]);
            __syncthreads();
            float inv = cs[task];
#pragma unroll
            for (int n = sg * 16; n < sg * 16 + 16; n++) Pp[n * P32 + D] *= inv;
        }
        __syncthreads();

        // ---- P4: op (partial o) and a, one phase
        {
            float acc[4][4];
#pragma unroll
            for (int i = 0; i < 4; i++)
#pragma unroll
                for (int j = 0; j < 4; j++) acc[i][j] = 0.f;
#pragma unroll 4
            for (int k = 0; k < 32; k++) {
                float a[4], bb[4];
#pragma unroll
                for (int i = 0; i < 4; i++) a[i]  = Pq[(r16 + 16 * i) * P32 + k];
#pragma unroll
                for (int j = 0; j < 4; j++) bb[j] = Wo_[k * P64 + c16 + 16 * j];
#pragma unroll
                for (int i = 0; i < 4; i++)
#pragma unroll
                    for (int j = 0; j < 4; j++) acc[i][j] += a[i] * bb[j];
            }
#pragma unroll
            for (int i = 0; i < 4; i++)
#pragma unroll
                for (int j = 0; j < 4; j++)
                    op[(r16 + 16 * i) * P64 + c16 + 16 * j] = acc[i][j];

            float av[2][4];
#pragma unroll
            for (int i = 0; i < 2; i++)
#pragma unroll
                for (int j = 0; j < 4; j++) av[i][j] = 0.f;
#pragma unroll 4
            for (int k = 0; k < 64; k++) {
                float v0 = V[r8 * P64 + k], v1 = V[(r8 + 32) * P64 + k];
                float bw[4];
#pragma unroll
                for (int j = 0; j < 4; j++) bw[j] = Wo_[(c8 + 8 * j) * P64 + k];
#pragma unroll
                for (int j = 0; j < 4; j++) {
                    av[0][j] += v0 * bw[j];
                    av[1][j] += v1 * bw[j];
                }
            }
#pragma unroll
            for (int j = 0; j < 4; j++) {
                Am[r8 * P32 + c8 + 8 * j]        = av[0][j];
                Am[(r8 + 32) * P32 + c8 + 8 * j] = av[1][j];
            }
        }
        __syncthreads();
        CLUSTER_SYNC();

        // ---- P5: o = op_self + op_peer (rows [rank*32, rank*32+32)); sp
        for (int i = t; i < 2048; i += 256) {
            int n = (int)rank * 32 + (i >> 6), d = i & 63;
            float v2 = op[n * P64 + d] + ld_dsmem(op_peer + (uint32_t)(n * P64 + d) * 4u);
            g_o[base + (size_t)n * 1024 + d] = v2;
        }
        if (t < 64) {
            float s = 0.f;
#pragma unroll 8
            for (int Dl = 0; Dl < 32; Dl++) s += Pk[t * P32 + Dl] * Am[t * P32 + Dl];
            sp[t] = s;
        }
        __syncthreads();
        CLUSTER_SYNC();

        // ---- P6: total s
        if (t < 64) ss[t] = sp[t] + ld_dsmem(sp_peer + (uint32_t)t * 4u);
        __syncthreads();

        // ---- P7: grads (g_z recomputed inline) + state update (8x32 grid)
        {
            float gin[4][2], gout[4][2];
#pragma unroll
            for (int i = 0; i < 4; i++) { gin[i][0] = gin[i][1] = 0.f; gout[i][0] = gout[i][1] = 0.f; }
#pragma unroll 4
            for (int n = 0; n < 64; n++) {
                float ssn = ss[n];
                float pk[4], am[4];
#pragma unroll
                for (int i = 0; i < 4; i++) {
                    pk[i] = Pk[n * P32 + rg + 8 * i];
                    am[i] = Am[n * P32 + rg + 8 * i];
                }
                float kk0 = Kt[n * P64 + cg], kk1 = Kt[n * P64 + cg + 32];
                float vv0 = V [n * P64 + cg], vv1 = V [n * P64 + cg + 32];
#pragma unroll
                for (int i = 0; i < 4; i++) {
                    float gz = -pk[i] * (am[i] - ssn);
                    gin[i][0]  += gz * kk0;
                    gin[i][1]  += gz * kk1;
                    gout[i][0] += pk[i] * vv0;
                    gout[i][1] += pk[i] * vv1;
                }
            }
#pragma unroll
            for (int i = 0; i < 4; i++) {
#pragma unroll
                for (int j = 0; j < 2; j++) {
                    int idx = (rg + 8 * i) * P64 + cg + 32 * j;
                    Wi [idx] = wdi * Wi [idx] - li * gin[i][j];
                    Wo_[idx] = wdo * Wo_[idx] + lo * gout[i][j];
                }
            }
        }
        __syncthreads();
    }
    CLUSTER_SYNC();   // keep smem alive for peer's in-flight DSMEM reads
}

// ---------------------------------------------------------------------------
// Launch
// ---------------------------------------------------------------------------
extern "C" void kernel_launch(void* const* d_in, const int* in_sizes, int n_in,
                              void* d_out, int out_size)
{
    (void)in_sizes; (void)n_in; (void)out_size;
    const float* x     = (const float*)d_in[0];
    const float* Wq    = (const float*)d_in[1];
    const float* Wk    = (const float*)d_in[2];
    const float* Wv    = (const float*)d_in[3];
    const float* Wlr   = (const float*)d_in[4];
    const float* Wbeta = (const float*)d_in[5];
    const float* Wo    = (const float*)d_in[6];
    const float* Win0  = (const float*)d_in[7];
    const float* Wout0 = (const float*)d_in[8];
    float* out = (float*)d_out;

    float *q, *k, *v, *om, *xt, *wt;
    cudaGetSymbolAddress((void**)&q,  g_q);
    cudaGetSymbolAddress((void**)&k,  g_k);
    cudaGetSymbolAddress((void**)&v,  g_v);
    cudaGetSymbolAddress((void**)&om, g_o);
    cudaGetSymbolAddress((void**)&xt, g_xt);
    cudaGetSymbolAddress((void**)&wt, g_wt);

    // unconditional (no static guards — harness contract): cheap host-side calls
    cudaFuncSetAttribute(gemm_tf32p<0>, cudaFuncAttributeMaxDynamicSharedMemorySize, GEMM_SMEM_BYTES);
    cudaFuncSetAttribute(gemm_tf32p<1>, cudaFuncAttributeMaxDynamicSharedMemorySize, GEMM_SMEM_BYTES);
    cudaFuncSetAttribute(scan_kernel,   cudaFuncAttributeMaxDynamicSharedMemorySize,
                         SCAN_SMEM_FLOATS * (int)sizeof(float));

    const int NX4 = (M_ * 1024) / 4;       // 4M float4
    const int NW4 = (1024 * 1024) / 4;     // 256K float4
    cvt_kernel<<<(NX4 + 255) / 256, 256>>>(x,  xt,            NX4);
    cvt_kernel<<<(NW4 + 255) / 256, 256>>>(Wq, wt + 0u * 1024u * 1024u, NW4);
    cvt_kernel<<<(NW4 + 255) / 256, 256>>>(Wk, wt + 1u * 1024u * 1024u, NW4);
    cvt_kernel<<<(NW4 + 255) / 256, 256>>>(Wv, wt + 2u * 1024u * 1024u, NW4);
    cvt_kernel<<<(NW4 + 255) / 256, 256>>>(Wo, wt + 3u * 1024u * 1024u, NW4);

    dim3 grid(1024 / 128, M_ / 128);
    gemm_tf32p<1><<<grid, 256, GEMM_SMEM_BYTES>>>(xt, wt + 0u * 1024u * 1024u, q, M_, 1024, 1024);
    gemm_tf32p<1><<<grid, 256, GEMM_SMEM_BYTES>>>(xt, wt + 1u * 1024u * 1024u, k, M_, 1024, 1024);
    gemm_tf32p<0><<<grid, 256, GEMM_SMEM_BYTES>>>(xt, wt + 2u * 1024u * 1024u, v, M_, 1024, 1024);
    lrwd_kernel<<<B_ * NCHUNK_, 256>>>(x, Wlr, Wbeta);

    const int smem_bytes = SCAN_SMEM_FLOATS * (int)sizeof(float);
    scan_kernel<<<128, 256, smem_bytes>>>(Win0, Wout0);

    // convert scan output to tf32 (reuse g_k as scratch), then final GEMM
    cvt_kernel<<<(NX4 + 255) / 256, 256>>>(om, k, NX4);
    gemm_tf32p<0><<<grid, 256, GEMM_SMEM_BYTES>>>(k, wt + 3u * 1024u * 1024u, out, M_, 1024, 1024);
}